// round 1
// baseline (speedup 1.0000x reference)
#include <cuda_runtime.h>

// ---------------------------------------------------------------------------
// MinkUNet backbone, fp32 implicit-GEMM implementation.
// Every layer is one templated tiled GEMM (64x64x32, 256 thr, 4x4 microtile)
// with three A-operand modes:
//   A_CONV   : A[m][kk] = f[nbr[m*KN + kk/Cin]][kk%Cin]   (gather conv)
//   A_CONCAT : A[m][kk] = kk<Ca ? fa[up[m]][kk] : fb[m][kk-Ca]
//   A_GATHER : A[m][kk] = f[idx[m]][kk]                   (final seed gemm)
// Epilogues: relu / residual+relu / transpose-store (final output layout).
// Final projection is done only on the 8192 gathered seed rows (saves ~9 GF
// and a 205MB buffer vs materializing out_vox for all 100k voxels).
// ---------------------------------------------------------------------------

#define KN0 100000
#define KN1 50000
#define KN2 25000
#define KN3 12500

// scratch feature maps (static device arrays: no allocation at runtime)
__device__ float g_x0a[KN0 * 32];
__device__ float g_x0b[KN0 * 32];
__device__ float g_x1a[KN1 * 64];
__device__ float g_x1b[KN1 * 64];
__device__ float g_x2a[KN2 * 128];
__device__ float g_x2b[KN2 * 128];
__device__ float g_x3a[KN3 * 256];
__device__ float g_x3b[KN3 * 256];
__device__ float g_u2[KN2 * 256];
__device__ float g_u1[KN1 * 128];
__device__ float g_u0[KN0 * 96];

#define A_CONV 0
#define A_CONCAT 1
#define A_GATHER 2

#define E_RELU 0
#define E_RES_RELU 1
#define E_TRANS 2

#define BM 64
#define BN 64
#define BK 32

template <int AMODE, int EPI>
__global__ __launch_bounds__(256) void gemm_k(
    const float* __restrict__ fA, const float* __restrict__ fB,
    const int* __restrict__ idx, const float* __restrict__ W,
    const float* __restrict__ res, float* __restrict__ out,
    int M, int Cout, int Kdim, int Cin, int KN, int Ca)
{
    __shared__ __align__(16) float As[BK][BM];   // stored transposed: As[k][m]
    __shared__ __align__(16) float Bs[BK][BN];

    const int tid = threadIdx.x;
    const int m0 = blockIdx.x * BM;
    const int n0 = blockIdx.y * BN;

    // A global-load mapping: 64 rows x 32 cols, each thread 8 contiguous floats
    const int ar = tid >> 2;            // row 0..63
    const int ac = (tid & 3) * 8;       // col base 0/8/16/24
    // B global-load mapping: 32 rows x 64 cols
    const int br = tid >> 3;            // k-row 0..31
    const int bc = (tid & 7) * 8;       // col base 0..56
    // compute mapping: 16x16 thread grid, 4x4 microtile
    const int tr = (tid >> 4) * 4;
    const int tc = (tid & 15) * 4;

    float acc[4][4] = {};

    for (int kt = 0; kt < Kdim; kt += BK) {
        // ---- stage A into registers ----
        float4 a0, a1;
        {
            const int m = m0 + ar;
            if (m < M) {
                const float* base;
                if (AMODE == A_CONV) {
                    const int kOff = kt / Cin;
                    const int ci0 = kt - kOff * Cin;
                    const int g = idx[(size_t)m * KN + kOff];
                    base = fA + (size_t)g * Cin + ci0;
                } else if (AMODE == A_CONCAT) {
                    if (kt < Ca) {
                        const int g = idx[m];
                        base = fA + (size_t)g * Ca + kt;
                    } else {
                        const int Cb = Kdim - Ca;
                        base = fB + (size_t)m * Cb + (kt - Ca);
                    }
                } else {  // A_GATHER
                    const int g = idx[m];
                    base = fA + (size_t)g * Kdim + kt;
                }
                a0 = *reinterpret_cast<const float4*>(base + ac);
                a1 = *reinterpret_cast<const float4*>(base + ac + 4);
            } else {
                a0 = make_float4(0.f, 0.f, 0.f, 0.f);
                a1 = a0;
            }
        }
        // ---- stage B into registers ----
        float4 b0, b1;
        {
            const int n = n0 + bc;
            if (n < Cout) {  // Cout and bc are multiples of 8 -> full-vec ok
                const float* wb = W + (size_t)(kt + br) * Cout + n;
                b0 = *reinterpret_cast<const float4*>(wb);
                b1 = *reinterpret_cast<const float4*>(wb + 4);
            } else {
                b0 = make_float4(0.f, 0.f, 0.f, 0.f);
                b1 = b0;
            }
        }

        __syncthreads();  // previous compute done reading smem
        As[ac + 0][ar] = a0.x; As[ac + 1][ar] = a0.y;
        As[ac + 2][ar] = a0.z; As[ac + 3][ar] = a0.w;
        As[ac + 4][ar] = a1.x; As[ac + 5][ar] = a1.y;
        As[ac + 6][ar] = a1.z; As[ac + 7][ar] = a1.w;
        *reinterpret_cast<float4*>(&Bs[br][bc])     = b0;
        *reinterpret_cast<float4*>(&Bs[br][bc + 4]) = b1;
        __syncthreads();

#pragma unroll
        for (int kk = 0; kk < BK; ++kk) {
            const float4 av = *reinterpret_cast<const float4*>(&As[kk][tr]);
            const float4 bv = *reinterpret_cast<const float4*>(&Bs[kk][tc]);
            const float a[4] = {av.x, av.y, av.z, av.w};
            const float b[4] = {bv.x, bv.y, bv.z, bv.w};
#pragma unroll
            for (int i = 0; i < 4; ++i)
#pragma unroll
                for (int j = 0; j < 4; ++j)
                    acc[i][j] = fmaf(a[i], b[j], acc[i][j]);
        }
    }

    // ---- epilogue ----
#pragma unroll
    for (int i = 0; i < 4; ++i) {
        const int m = m0 + tr + i;
        if (m >= M) continue;
#pragma unroll
        for (int j = 0; j < 4; ++j) {
            const int n = n0 + tc + j;
            if (n >= Cout) continue;
            float v = acc[i][j];
            if (EPI == E_RELU) {
                v = fmaxf(v, 0.f);
                out[(size_t)m * Cout + n] = v;
            } else if (EPI == E_RES_RELU) {
                v = res[(size_t)m * Cout + n] + fmaxf(v, 0.f);
                out[(size_t)m * Cout + n] = v;
            } else {  // E_TRANS: out[b][c][s], m = b*1024+s  (no relu)
                const int bb = m >> 10;
                const int ss = m & 1023;
                out[((size_t)bb * Cout + n) * 1024 + ss] = v;
            }
        }
    }
}

// Stem: Cin=3 (not a multiple of 32) -> dedicated kernel.
// x0[n][co] = relu(sum_{k<27,c<3} feats[nbr0[n][k]][c] * W[k][c][co]), co<32.
__global__ __launch_bounds__(256) void stem_k(
    const float* __restrict__ feats, const int* __restrict__ nbr,
    const float* __restrict__ W, float* __restrict__ out, int M)
{
    __shared__ float sW[27 * 3 * 32];   // 2592 floats
    __shared__ float sg[8][81];
    __shared__ int   sidx[8][27];
    const int tid = threadIdx.x;
    const int m0 = blockIdx.x * 8;

    for (int i = tid; i < 27 * 96; i += 256) sW[i] = W[i];
    for (int i = tid; i < 8 * 27; i += 256) {
        const int r = i / 27, k = i % 27;
        const int m = m0 + r;
        sidx[r][k] = (m < M) ? nbr[(size_t)m * 27 + k] : 0;
    }
    __syncthreads();
    for (int i = tid; i < 8 * 81; i += 256) {
        const int r = i / 81, j = i % 81;
        const int k = j / 3, c = j % 3;
        sg[r][j] = feats[(size_t)sidx[r][k] * 3 + c];
    }
    __syncthreads();

    const int r = tid >> 5;       // row within block
    const int co = tid & 31;      // out channel
    const int m = m0 + r;
    float acc = 0.f;
#pragma unroll
    for (int j = 0; j < 81; ++j)
        acc = fmaf(sg[r][j], sW[j * 32 + co], acc);
    if (m < M) out[(size_t)m * 32 + co] = fmaxf(acc, 0.f);
}

static float* sym(const void* s) {
    void* p = nullptr;
    cudaGetSymbolAddress(&p, s);
    return (float*)p;
}

extern "C" void kernel_launch(void* const* d_in, const int* in_sizes, int n_in,
                              void* d_out, int out_size)
{
    const float* feats  = (const float*)d_in[0];
    const int* nbr0     = (const int*)d_in[1];
    const int* nbr1     = (const int*)d_in[2];
    const int* nbr2     = (const int*)d_in[3];
    const int* nbr3     = (const int*)d_in[4];
    const int* down1    = (const int*)d_in[5];
    const int* down2    = (const int*)d_in[6];
    const int* down3    = (const int*)d_in[7];
    const int* up2      = (const int*)d_in[8];
    const int* up1      = (const int*)d_in[9];
    const int* up0      = (const int*)d_in[10];
    const int* seed_idx = (const int*)d_in[11];
    const float* W_stem = (const float*)d_in[12];
    const float* W_b0   = (const float*)d_in[13];
    const float* W_d1   = (const float*)d_in[14];
    const float* W_b1   = (const float*)d_in[15];
    const float* W_d2   = (const float*)d_in[16];
    const float* W_b2   = (const float*)d_in[17];
    const float* W_d3   = (const float*)d_in[18];
    const float* W_b3   = (const float*)d_in[19];
    const float* W_u2   = (const float*)d_in[20];
    const float* W_u1   = (const float*)d_in[21];
    const float* W_u0   = (const float*)d_in[22];
    const float* W_out  = (const float*)d_in[23];
    float* out = (float*)d_out;

    float* x0a = sym(g_x0a); float* x0b = sym(g_x0b);
    float* x1a = sym(g_x1a); float* x1b = sym(g_x1b);
    float* x2a = sym(g_x2a); float* x2b = sym(g_x2b);
    float* x3a = sym(g_x3a); float* x3b = sym(g_x3b);
    float* u2  = sym(g_u2);  float* u1  = sym(g_u1);  float* u0 = sym(g_u0);

    const int M0 = KN0, M1 = KN1, M2 = KN2, M3 = KN3;
    auto grd = [](int M, int Cout) {
        return dim3((unsigned)((M + BM - 1) / BM), (unsigned)((Cout + BN - 1) / BN));
    };

    // ---- encoder ----
    stem_k<<<(M0 + 7) / 8, 256>>>(feats, nbr0, W_stem, x0a, M0);

    gemm_k<A_CONV, E_RES_RELU><<<grd(M0, 32), 256>>>(
        x0a, nullptr, nbr0, W_b0, x0a, x0b, M0, 32, 27 * 32, 32, 27, 0);

    gemm_k<A_CONV, E_RELU><<<grd(M1, 64), 256>>>(
        x0b, nullptr, down1, W_d1, nullptr, x1a, M1, 64, 8 * 32, 32, 8, 0);
    gemm_k<A_CONV, E_RES_RELU><<<grd(M1, 64), 256>>>(
        x1a, nullptr, nbr1, W_b1, x1a, x1b, M1, 64, 27 * 64, 64, 27, 0);

    gemm_k<A_CONV, E_RELU><<<grd(M2, 128), 256>>>(
        x1b, nullptr, down2, W_d2, nullptr, x2a, M2, 128, 8 * 64, 64, 8, 0);
    gemm_k<A_CONV, E_RES_RELU><<<grd(M2, 128), 256>>>(
        x2a, nullptr, nbr2, W_b2, x2a, x2b, M2, 128, 27 * 128, 128, 27, 0);

    gemm_k<A_CONV, E_RELU><<<grd(M3, 256), 256>>>(
        x2b, nullptr, down3, W_d3, nullptr, x3a, M3, 256, 8 * 128, 128, 8, 0);
    gemm_k<A_CONV, E_RES_RELU><<<grd(M3, 256), 256>>>(
        x3a, nullptr, nbr3, W_b3, x3a, x3b, M3, 256, 27 * 256, 256, 27, 0);

    // ---- decoder ----
    gemm_k<A_CONCAT, E_RELU><<<grd(M2, 256), 256>>>(
        x3b, x2b, up2, W_u2, nullptr, u2, M2, 256, 384, 0, 0, 256);
    gemm_k<A_CONCAT, E_RELU><<<grd(M1, 128), 256>>>(
        u2, x1b, up1, W_u1, nullptr, u1, M1, 128, 320, 0, 0, 256);
    gemm_k<A_CONCAT, E_RELU><<<grd(M0, 96), 256>>>(
        u1, x0b, up0, W_u0, nullptr, u0, M0, 96, 160, 0, 0, 128);

    // ---- final: gather 8192 seed rows, project to 512, transpose-store ----
    gemm_k<A_GATHER, E_TRANS><<<grd(8 * 1024, 512), 256>>>(
        u0, nullptr, seed_idx, W_out, nullptr, out, 8 * 1024, 512, 96, 0, 0, 0);
}

// round 2
// speedup vs baseline: 1.1490x; 1.1490x over previous
#include <cuda_runtime.h>

// ---------------------------------------------------------------------------
// MinkUNet backbone, fp32 implicit-GEMM, round 2:
//  - per-layer tile configs (128x128 / 128x64 / 128x32), 8x8 / 8x4 / 4x4 micro
//  - double-buffered shared memory, register-staged global loads
//  - padded A-smem (+4) to reduce STS bank conflicts
// A-operand modes: gather-conv / concat / plain-gather. Epilogues: relu,
// residual+relu, transpose-store.
// ---------------------------------------------------------------------------

#define KN0 100000
#define KN1 50000
#define KN2 25000
#define KN3 12500

__device__ float g_x0a[KN0 * 32];
__device__ float g_x0b[KN0 * 32];
__device__ float g_x1a[KN1 * 64];
__device__ float g_x1b[KN1 * 64];
__device__ float g_x2a[KN2 * 128];
__device__ float g_x2b[KN2 * 128];
__device__ float g_x3a[KN3 * 256];
__device__ float g_x3b[KN3 * 256];
__device__ float g_u2[KN2 * 256];
__device__ float g_u1[KN1 * 128];
__device__ float g_u0[KN0 * 96];

#define A_CONV 0
#define A_CONCAT 1
#define A_GATHER 2

#define E_RELU 0
#define E_RES_RELU 1
#define E_TRANS 2

template <int BM, int BN, int BK, int TM, int TN, int AMODE, int EPI>
__global__ __launch_bounds__((BM / TM) * (BN / TN), 2) void gemm_k(
    const float* __restrict__ fA, const float* __restrict__ fB,
    const int* __restrict__ idx, const float* __restrict__ W,
    const float* __restrict__ res, float* __restrict__ out,
    int M, int Cout, int Kdim, int Cin, int KN, int Ca)
{
    constexpr int THREADS = (BM / TM) * (BN / TN);
    constexpr int BMP = BM + 4;                 // padded A rows
    constexpr int A4 = BM * BK / 4;             // float4 count, A tile
    constexpr int B4 = BK * BN / 4;             // float4 count, B tile
    constexpr int NA = (A4 + THREADS - 1) / THREADS;
    constexpr int NB = (B4 + THREADS - 1) / THREADS;
    constexpr bool AEX = (A4 % THREADS) == 0;
    constexpr bool BEX = (B4 % THREADS) == 0;
    constexpr int BK4 = BK / 4;
    constexpr int BN4 = BN / 4;

    __shared__ __align__(16) float As[2][BK][BMP];
    __shared__ __align__(16) float Bs[2][BK][BN];

    const int tid = threadIdx.x;
    const int m0 = blockIdx.x * BM;
    const int n0 = blockIdx.y * BN;
    const int tx = tid % (BN / TN);
    const int ty = tid / (BN / TN);

    float4 ra[NA];
    float4 rb[NB];
    float acc[TM][TN] = {};

    const int ntile = Kdim / BK;   // all layer K dims are multiples of BK

    auto load_tile = [&](int it) {
        const int kt = it * BK;
        int kOff = 0, ci0 = 0;
        if (AMODE == A_CONV) { kOff = kt / Cin; ci0 = kt - kOff * Cin; }
#pragma unroll
        for (int t = 0; t < NA; ++t) {
            const int i4 = tid + t * THREADS;
            if (AEX || i4 < A4) {
                const int row = i4 / BK4;
                const int c4 = (i4 - row * BK4) * 4;
                const int m = m0 + row;
                float4 v = make_float4(0.f, 0.f, 0.f, 0.f);
                if (m < M) {
                    const float* p;
                    if (AMODE == A_CONV) {
                        const int g = idx[(size_t)m * KN + kOff];
                        p = fA + (size_t)g * Cin + ci0 + c4;
                    } else if (AMODE == A_CONCAT) {
                        if (kt < Ca) {
                            const int g = idx[m];
                            p = fA + (size_t)g * Ca + kt + c4;
                        } else {
                            p = fB + (size_t)m * (Kdim - Ca) + (kt - Ca) + c4;
                        }
                    } else {
                        const int g = idx[m];
                        p = fA + (size_t)g * Kdim + kt + c4;
                    }
                    v = *reinterpret_cast<const float4*>(p);
                }
                ra[t] = v;
            }
        }
#pragma unroll
        for (int t = 0; t < NB; ++t) {
            const int i4 = tid + t * THREADS;
            if (BEX || i4 < B4) {
                const int row = i4 / BN4;
                const int c = (i4 - row * BN4) * 4;
                const int n = n0 + c;
                float4 v = make_float4(0.f, 0.f, 0.f, 0.f);
                if (n < Cout)
                    v = *reinterpret_cast<const float4*>(W + (size_t)(kt + row) * Cout + n);
                rb[t] = v;
            }
        }
    };

    auto store_tile = [&](int buf) {
#pragma unroll
        for (int t = 0; t < NA; ++t) {
            const int i4 = tid + t * THREADS;
            if (AEX || i4 < A4) {
                const int row = i4 / BK4;
                const int c4 = (i4 - row * BK4) * 4;
                As[buf][c4 + 0][row] = ra[t].x;
                As[buf][c4 + 1][row] = ra[t].y;
                As[buf][c4 + 2][row] = ra[t].z;
                As[buf][c4 + 3][row] = ra[t].w;
            }
        }
#pragma unroll
        for (int t = 0; t < NB; ++t) {
            const int i4 = tid + t * THREADS;
            if (BEX || i4 < B4) {
                const int row = i4 / BN4;
                const int c = (i4 - row * BN4) * 4;
                *reinterpret_cast<float4*>(&Bs[buf][row][c]) = rb[t];
            }
        }
    };

    load_tile(0);
    store_tile(0);
    __syncthreads();

    int buf = 0;
    for (int it = 0; it < ntile; ++it) {
        if (it + 1 < ntile) load_tile(it + 1);
#pragma unroll
        for (int kk = 0; kk < BK; ++kk) {
            float a[TM], b[TN];
#pragma unroll
            for (int i = 0; i < TM; i += 4) {
                const float4 v = *reinterpret_cast<const float4*>(&As[buf][kk][ty * TM + i]);
                a[i] = v.x; a[i + 1] = v.y; a[i + 2] = v.z; a[i + 3] = v.w;
            }
#pragma unroll
            for (int j = 0; j < TN; j += 4) {
                const float4 v = *reinterpret_cast<const float4*>(&Bs[buf][kk][tx * TN + j]);
                b[j] = v.x; b[j + 1] = v.y; b[j + 2] = v.z; b[j + 3] = v.w;
            }
#pragma unroll
            for (int i = 0; i < TM; ++i)
#pragma unroll
                for (int j = 0; j < TN; ++j)
                    acc[i][j] = fmaf(a[i], b[j], acc[i][j]);
        }
        if (it + 1 < ntile) store_tile(buf ^ 1);
        __syncthreads();
        buf ^= 1;
    }

    // ---- epilogue ----
    const int rbase = m0 + ty * TM;
    const int cbase = n0 + tx * TN;
    if (EPI != E_TRANS && (n0 + BN) <= Cout) {
        // fully in-range n-block: vectorized stores
#pragma unroll
        for (int i = 0; i < TM; ++i) {
            const int m = rbase + i;
            if (m >= M) continue;
#pragma unroll
            for (int j = 0; j < TN; j += 4) {
                float4 v;
                v.x = fmaxf(acc[i][j + 0], 0.f);
                v.y = fmaxf(acc[i][j + 1], 0.f);
                v.z = fmaxf(acc[i][j + 2], 0.f);
                v.w = fmaxf(acc[i][j + 3], 0.f);
                if (EPI == E_RES_RELU) {
                    const float4 r = *reinterpret_cast<const float4*>(
                        res + (size_t)m * Cout + cbase + j);
                    v.x += r.x; v.y += r.y; v.z += r.z; v.w += r.w;
                }
                *reinterpret_cast<float4*>(out + (size_t)m * Cout + cbase + j) = v;
            }
        }
    } else {
#pragma unroll
        for (int i = 0; i < TM; ++i) {
            const int m = rbase + i;
            if (m >= M) continue;
#pragma unroll
            for (int j = 0; j < TN; ++j) {
                const int n = cbase + j;
                if (n >= Cout) continue;
                float v = acc[i][j];
                if (EPI == E_TRANS) {
                    // out[b][c][s]; m = b*1024 + s  (no relu on final gemm)
                    const int bb = m >> 10;
                    const int ss = m & 1023;
                    out[((size_t)bb * Cout + n) * 1024 + ss] = v;
                } else {
                    v = fmaxf(v, 0.f);
                    if (EPI == E_RES_RELU) v += res[(size_t)m * Cout + n];
                    out[(size_t)m * Cout + n] = v;
                }
            }
        }
    }
}

// Stem: Cin=3 -> dedicated kernel.
__global__ __launch_bounds__(256) void stem_k(
    const float* __restrict__ feats, const int* __restrict__ nbr,
    const float* __restrict__ W, float* __restrict__ out, int M)
{
    __shared__ float sW[27 * 3 * 32];
    __shared__ float sg[8][81];
    __shared__ int   sidx[8][27];
    const int tid = threadIdx.x;
    const int m0 = blockIdx.x * 8;

    for (int i = tid; i < 27 * 96; i += 256) sW[i] = W[i];
    for (int i = tid; i < 8 * 27; i += 256) {
        const int r = i / 27, k = i % 27;
        const int m = m0 + r;
        sidx[r][k] = (m < M) ? nbr[(size_t)m * 27 + k] : 0;
    }
    __syncthreads();
    for (int i = tid; i < 8 * 81; i += 256) {
        const int r = i / 81, j = i % 81;
        const int k = j / 3, c = j % 3;
        sg[r][j] = feats[(size_t)sidx[r][k] * 3 + c];
    }
    __syncthreads();

    const int r = tid >> 5;
    const int co = tid & 31;
    const int m = m0 + r;
    float acc = 0.f;
#pragma unroll
    for (int j = 0; j < 81; ++j)
        acc = fmaf(sg[r][j], sW[j * 32 + co], acc);
    if (m < M) out[(size_t)m * 32 + co] = fmaxf(acc, 0.f);
}

static float* sym(const void* s) {
    void* p = nullptr;
    cudaGetSymbolAddress(&p, s);
    return (float*)p;
}

// tile configs
#define BIG 128, 128, 16, 8, 8
#define MED 128, 64, 16, 8, 4
#define SML 128, 32, 16, 4, 4

extern "C" void kernel_launch(void* const* d_in, const int* in_sizes, int n_in,
                              void* d_out, int out_size)
{
    const float* feats  = (const float*)d_in[0];
    const int* nbr0     = (const int*)d_in[1];
    const int* nbr1     = (const int*)d_in[2];
    const int* nbr2     = (const int*)d_in[3];
    const int* nbr3     = (const int*)d_in[4];
    const int* down1    = (const int*)d_in[5];
    const int* down2    = (const int*)d_in[6];
    const int* down3    = (const int*)d_in[7];
    const int* up2      = (const int*)d_in[8];
    const int* up1      = (const int*)d_in[9];
    const int* up0      = (const int*)d_in[10];
    const int* seed_idx = (const int*)d_in[11];
    const float* W_stem = (const float*)d_in[12];
    const float* W_b0   = (const float*)d_in[13];
    const float* W_d1   = (const float*)d_in[14];
    const float* W_b1   = (const float*)d_in[15];
    const float* W_d2   = (const float*)d_in[16];
    const float* W_b2   = (const float*)d_in[17];
    const float* W_d3   = (const float*)d_in[18];
    const float* W_b3   = (const float*)d_in[19];
    const float* W_u2   = (const float*)d_in[20];
    const float* W_u1   = (const float*)d_in[21];
    const float* W_u0   = (const float*)d_in[22];
    const float* W_out  = (const float*)d_in[23];
    float* out = (float*)d_out;

    float* x0a = sym(g_x0a); float* x0b = sym(g_x0b);
    float* x1a = sym(g_x1a); float* x1b = sym(g_x1b);
    float* x2a = sym(g_x2a); float* x2b = sym(g_x2b);
    float* x3a = sym(g_x3a); float* x3b = sym(g_x3b);
    float* u2  = sym(g_u2);  float* u1  = sym(g_u1);  float* u0 = sym(g_u0);

    const int M0 = KN0, M1 = KN1, M2 = KN2, M3 = KN3;
    auto grd = [](int M, int Cout, int bm, int bn) {
        return dim3((unsigned)((M + bm - 1) / bm), (unsigned)((Cout + bn - 1) / bn));
    };

    // ---- encoder ----
    stem_k<<<(M0 + 7) / 8, 256>>>(feats, nbr0, W_stem, x0a, M0);

    gemm_k<SML, A_CONV, E_RES_RELU><<<grd(M0, 32, 128, 32), 256>>>(
        x0a, nullptr, nbr0, W_b0, x0a, x0b, M0, 32, 27 * 32, 32, 27, 0);

    gemm_k<MED, A_CONV, E_RELU><<<grd(M1, 64, 128, 64), 256>>>(
        x0b, nullptr, down1, W_d1, nullptr, x1a, M1, 64, 8 * 32, 32, 8, 0);
    gemm_k<MED, A_CONV, E_RES_RELU><<<grd(M1, 64, 128, 64), 256>>>(
        x1a, nullptr, nbr1, W_b1, x1a, x1b, M1, 64, 27 * 64, 64, 27, 0);

    gemm_k<BIG, A_CONV, E_RELU><<<grd(M2, 128, 128, 128), 256>>>(
        x1b, nullptr, down2, W_d2, nullptr, x2a, M2, 128, 8 * 64, 64, 8, 0);
    gemm_k<BIG, A_CONV, E_RES_RELU><<<grd(M2, 128, 128, 128), 256>>>(
        x2a, nullptr, nbr2, W_b2, x2a, x2b, M2, 128, 27 * 128, 128, 27, 0);

    gemm_k<BIG, A_CONV, E_RELU><<<grd(M3, 256, 128, 128), 256>>>(
        x2b, nullptr, down3, W_d3, nullptr, x3a, M3, 256, 8 * 128, 128, 8, 0);
    gemm_k<BIG, A_CONV, E_RES_RELU><<<grd(M3, 256, 128, 128), 256>>>(
        x3a, nullptr, nbr3, W_b3, x3a, x3b, M3, 256, 27 * 256, 256, 27, 0);

    // ---- decoder ----
    gemm_k<BIG, A_CONCAT, E_RELU><<<grd(M2, 256, 128, 128), 256>>>(
        x3b, x2b, up2, W_u2, nullptr, u2, M2, 256, 384, 0, 0, 256);
    gemm_k<BIG, A_CONCAT, E_RELU><<<grd(M1, 128, 128, 128), 256>>>(
        u2, x1b, up1, W_u1, nullptr, u1, M1, 128, 320, 0, 0, 256);
    gemm_k<MED, A_CONCAT, E_RELU><<<grd(M0, 96, 128, 64), 256>>>(
        u1, x0b, up0, W_u0, nullptr, u0, M0, 96, 160, 0, 0, 128);

    // ---- final: gather 8192 seed rows, project to 512, transpose-store ----
    gemm_k<BIG, A_GATHER, E_TRANS><<<grd(8 * 1024, 512, 128, 128), 256>>>(
        u0, nullptr, seed_idx, W_out, nullptr, out, 8 * 1024, 512, 96, 0, 0, 0);
}

// round 4
// speedup vs baseline: 2.4043x; 2.0924x over previous
#include <cuda_runtime.h>
#include <cuda_bf16.h>
#include <cstdint>

// ---------------------------------------------------------------------------
// MinkUNet backbone, round 4: tcgen05 bf16 "double-double" implicit GEMM.
// Identical to round 3 except all tcgen05 inline-asm is guarded with
// __CUDA_ARCH_FEAT_SM103_ALL so the harness's plain compute_103 PTX fallback
// pass compiles (stubs); the sm_103a cubin carries the real tensor path.
// ---------------------------------------------------------------------------

#define KN0 100000
#define KN1 50000
#define KN2 25000
#define KN3 12500

__device__ float g_x0a[KN0 * 32];
__device__ float g_x0b[KN0 * 32];
__device__ float g_x1a[KN1 * 64];
__device__ float g_x1b[KN1 * 64];
__device__ float g_x2a[KN2 * 128];
__device__ float g_x2b[KN2 * 128];
__device__ float g_x3a[KN3 * 256];
__device__ float g_x3b[KN3 * 256];
__device__ float g_u2[KN2 * 256];
__device__ float g_u1[KN1 * 128];
__device__ float g_u0[KN0 * 96];

#define WDECL(name, npad, kpad) \
    __device__ uint4 name##h[(npad) * (kpad) / 8]; \
    __device__ uint4 name##l[(npad) * (kpad) / 8];
WDECL(w_b0, 32, 896)
WDECL(w_d1, 64, 256)
WDECL(w_b1, 64, 1728)
WDECL(w_d2, 128, 512)
WDECL(w_b2, 128, 3456)
WDECL(w_d3, 256, 1024)
WDECL(w_b3, 256, 6912)
WDECL(w_u2, 256, 384)
WDECL(w_u1, 128, 320)
WDECL(w_u0, 128, 192)

#define A_CONV 0
#define A_CONCAT 1
#define E_RELU 0
#define E_RES_RELU 1

// Guard: tcgen05 exists only in the sm_103a ('a'-feature) compile pass.
#if defined(__CUDA_ARCH__) && !defined(__CUDA_ARCH_FEAT_SM103_ALL)
#define NO_TC 1
#endif

// ---------------- PTX helpers ----------------
__device__ __forceinline__ uint32_t smem_u32(const void* p) {
    uint32_t a;
    asm("{ .reg .u64 t; cvta.to.shared.u64 t, %1; cvt.u32.u64 %0, t; }" : "=r"(a) : "l"(p));
    return a;
}
__device__ __forceinline__ uint32_t elect_one() {
    uint32_t p;
    asm volatile("{ .reg .pred p; elect.sync _|p, 0xFFFFFFFF; selp.b32 %0, 1, 0, p; }" : "=r"(p));
    return p;
}
#define MBAR_INIT(a, c) asm volatile("mbarrier.init.shared.b64 [%0], %1;" :: "r"(a), "r"(c) : "memory")
#define MBAR_INVAL(a)   asm volatile("mbarrier.inval.shared.b64 [%0];" :: "r"(a) : "memory")
#define MBAR_WAIT(a, ph) do { \
    uint32_t _m = (a), _p = (ph), _d; \
    asm volatile("{ .reg .pred p; mbarrier.try_wait.parity.acquire.cta.shared::cta.b64 p, [%1], %2; selp.b32 %0,1,0,p; }" \
                 : "=r"(_d) : "r"(_m), "r"(_p) : "memory"); \
    if (!_d) { \
        asm volatile("{ .reg .pred P1; WL_%=: mbarrier.try_wait.parity.acquire.cta.shared::cta.b64 P1, [%0], %1, 0x989680; @P1 bra.uni WD_%=; bra.uni WL_%=; WD_%=: }" \
                     :: "r"(_m), "r"(_p) : "memory"); \
    } } while (0)
#define FENCE_ASYNC() asm volatile("fence.proxy.async.shared::cta;" ::: "memory")

#ifdef NO_TC
// inert stubs for the compute_103 fallback PTX pass (never executed at runtime)
#define TC_ALLOC(sa, n)   ((void)0)
#define TC_DEALLOC(t, n)  ((void)0)
#define TC_RELINQ()       ((void)0)
#define TC_COMMIT(a)      ((void)0)
#define TC_FENCE_AFTER()  ((void)0)
#define TC_FENCE_BEFORE() ((void)0)
#define TC_WAIT_LD()      ((void)0)
#define TC_LD_X32(r, ta)  do { _Pragma("unroll") for (int _i = 0; _i < 32; ++_i) (r)[_i] = 0u; } while (0)
__device__ __forceinline__ void mma_bf16_ss(uint32_t, uint64_t, uint64_t, uint32_t, uint32_t) {}
#else
#define TC_ALLOC(sa, n)   asm volatile("tcgen05.alloc.cta_group::1.sync.aligned.shared::cta.b32 [%0], %1;" :: "r"(sa), "r"(n) : "memory")
#define TC_DEALLOC(t, n)  asm volatile("tcgen05.dealloc.cta_group::1.sync.aligned.b32 %0, %1;" :: "r"(t), "r"(n))
#define TC_RELINQ()       asm volatile("tcgen05.relinquish_alloc_permit.cta_group::1.sync.aligned;")
#define TC_COMMIT(a)      asm volatile("tcgen05.commit.cta_group::1.mbarrier::arrive::one.shared::cluster.b64 [%0];" :: "r"(a) : "memory")
#define TC_FENCE_AFTER()  asm volatile("tcgen05.fence::after_thread_sync;" ::: "memory")
#define TC_FENCE_BEFORE() asm volatile("tcgen05.fence::before_thread_sync;" ::: "memory")
#define TC_WAIT_LD()      asm volatile("tcgen05.wait::ld.sync.aligned;" ::: "memory")
#define TC_LD_X32(r, ta) \
    asm volatile("tcgen05.ld.sync.aligned.32x32b.x32.b32 {%0,%1,%2,%3,%4,%5,%6,%7,%8,%9,%10,%11,%12,%13,%14,%15,%16,%17,%18,%19,%20,%21,%22,%23,%24,%25,%26,%27,%28,%29,%30,%31}, [%32];" \
        : "=r"((r)[0]), "=r"((r)[1]), "=r"((r)[2]), "=r"((r)[3]), "=r"((r)[4]), "=r"((r)[5]), "=r"((r)[6]), "=r"((r)[7]), \
          "=r"((r)[8]), "=r"((r)[9]), "=r"((r)[10]), "=r"((r)[11]), "=r"((r)[12]), "=r"((r)[13]), "=r"((r)[14]), "=r"((r)[15]), \
          "=r"((r)[16]), "=r"((r)[17]), "=r"((r)[18]), "=r"((r)[19]), "=r"((r)[20]), "=r"((r)[21]), "=r"((r)[22]), "=r"((r)[23]), \
          "=r"((r)[24]), "=r"((r)[25]), "=r"((r)[26]), "=r"((r)[27]), "=r"((r)[28]), "=r"((r)[29]), "=r"((r)[30]), "=r"((r)[31]) \
        : "r"(ta))
__device__ __forceinline__ void mma_bf16_ss(uint32_t d, uint64_t ad, uint64_t bd,
                                            uint32_t idesc, uint32_t acc) {
    asm volatile(
        "{ .reg .pred p; setp.ne.u32 p, %5, 0;\n\t"
        "tcgen05.mma.cta_group::1.kind::f16 [%0], %1, %2, %3, {%4,%4,%4,%4}, p; }"
        :: "r"(d), "l"(ad), "l"(bd), "r"(idesc), "r"(0u), "r"(acc) : "memory");
}
#endif

// SW128 K-major descriptor: layout=2, version=1, SBO=64, LBO=1
__device__ __forceinline__ uint64_t mk_desc(uint32_t addr) {
    const uint64_t base = (uint64_t(2) << 61) | (uint64_t(1) << 46) |
                          (uint64_t(64) << 32) | (uint64_t(1) << 16);
    return base | ((uint64_t)(addr >> 4) & 0x3FFF);
}
__device__ __forceinline__ uint32_t sw128(uint32_t off) {
    return off ^ ((off >> 3) & 0x70);
}
// split 2 floats into packed hi/lo bf16x2 (memory order x0 then x1)
__device__ __forceinline__ void split2(float x0, float x1, uint32_t& h, uint32_t& l) {
    uint32_t hp;
    asm("cvt.rn.satfinite.bf16x2.f32 %0, %1, %2;" : "=r"(hp) : "f"(x1), "f"(x0));
    float h0 = __uint_as_float(hp << 16);
    float h1 = __uint_as_float(hp & 0xFFFF0000u);
    float l0 = x0 - h0, l1 = x1 - h1;
    uint32_t lp;
    asm("cvt.rn.satfinite.bf16x2.f32 %0, %1, %2;" : "=r"(lp) : "f"(l1), "f"(l0));
    h = hp; l = lp;
}

// ---------------- tensor-core gather GEMM ----------------
// Tile: M=128 x N=NT, BK=64 fp32 (128B bf16 rows), 2-stage pipeline.
template <int NT, int AMODE, int EPI>
__global__ __launch_bounds__(256, 1) void tc_gemm(
    const float* __restrict__ fA, const float* __restrict__ fB,
    const int* __restrict__ idx,
    const uint4* __restrict__ Wh, const uint4* __restrict__ Wl,
    const float* __restrict__ res, float* __restrict__ out,
    int M, int Cout, int Kdim, int Kpad, int Cin, int KN, int Ca)
{
    constexpr int AB = 128 * 128;          // bytes per A subtile
    constexpr int BB = NT * 128;           // bytes per B subtile
    constexpr int STAGE = 2 * AB + 2 * BB;
    constexpr uint32_t IDESC =
        (1u << 4) | (1u << 7) | (1u << 10) | ((NT / 8) << 17) | (8u << 24);

    extern __shared__ char dsm[];
    __shared__ uint32_t s_tmem[1];
    __shared__ __align__(16) unsigned long long s_mbar[2];

    const int tid = threadIdx.x;
    const int wid = tid >> 5;
    const int lid = tid & 31;

    const uint32_t raw = smem_u32(dsm);
    const uint32_t sb = (raw + 1023u) & ~1023u;
    char* tiles = dsm + (sb - raw);

    const uint32_t mb0 = smem_u32(&s_mbar[0]);
    const uint32_t mb1 = mb0 + 8;
    const uint32_t tptr = smem_u32(&s_tmem[0]);

    if (wid == 0) TC_ALLOC(tptr, 256);
    if (tid == 0) { MBAR_INIT(mb0, 1); MBAR_INIT(mb1, 1); }
    __syncthreads();
    const uint32_t tmem = s_tmem[0];

    const int m0 = blockIdx.x * 128;
    const int ntile = Kpad / 64;
    const int ar = tid >> 1;              // A row 0..127
    const int ac0 = (tid & 1) * 4;        // first of 4 chunks (16B each)
    const int m = m0 + ar;

    const uint64_t dAh0 = mk_desc(sb);
    const uint64_t dAl0 = mk_desc(sb + AB);
    const uint64_t dBh0 = mk_desc(sb + 2 * AB);
    const uint64_t dBl0 = mk_desc(sb + 2 * AB + BB);

    int use0 = 0, use1 = 0;

    for (int t = 0; t < ntile; ++t) {
        const int b = t & 1;
        const uint32_t mb = b ? mb1 : mb0;
        const int use = b ? use1 : use0;
        if (use > 0) MBAR_WAIT(mb, (use - 1) & 1);

        char* Ah = tiles + b * STAGE;
        char* Al = Ah + AB;
        char* Bh = tiles + b * STAGE + 2 * AB;
        char* Bl = Bh + BB;
        const int kt = t * 64;

        // ---- gather + split A ----
#pragma unroll
        for (int c = ac0; c < ac0 + 4; ++c) {
            const int kk = kt + c * 8;
            float4 v0 = make_float4(0.f, 0.f, 0.f, 0.f), v1 = v0;
            if (m < M && kk < Kdim) {
                const float* p;
                if (AMODE == A_CONV) {
                    const int kOff = kk / Cin;
                    const int ci = kk - kOff * Cin;
                    const int g = idx[(size_t)m * KN + kOff];
                    p = fA + (size_t)g * Cin + ci;
                } else {  // A_CONCAT
                    if (kk < Ca) {
                        const int g = idx[m];
                        p = fA + (size_t)g * Ca + kk;
                    } else {
                        p = fB + (size_t)m * (Kdim - Ca) + (kk - Ca);
                    }
                }
                v0 = *reinterpret_cast<const float4*>(p);
                v1 = *reinterpret_cast<const float4*>(p + 4);
            }
            uint4 hv, lv;
            split2(v0.x, v0.y, hv.x, lv.x);
            split2(v0.z, v0.w, hv.y, lv.y);
            split2(v1.x, v1.y, hv.z, lv.z);
            split2(v1.z, v1.w, hv.w, lv.w);
            const uint32_t sw = sw128((uint32_t)(ar * 128 + c * 16));
            *reinterpret_cast<uint4*>(Ah + sw) = hv;
            *reinterpret_cast<uint4*>(Al + sw) = lv;
        }
        // ---- load B (pre-split, padded: unconditional) ----
        const int kq = kt / 8;
        const int kpq = Kpad / 8;
        for (int i = tid; i < NT * 8; i += 256) {
            const int n = i >> 3, j = i & 7;
            const uint4 h = Wh[(size_t)n * kpq + kq + j];
            const uint4 l = Wl[(size_t)n * kpq + kq + j];
            const uint32_t sw = sw128((uint32_t)(n * 128 + j * 16));
            *reinterpret_cast<uint4*>(Bh + sw) = h;
            *reinterpret_cast<uint4*>(Bl + sw) = l;
        }
        FENCE_ASYNC();
        __syncthreads();

        // ---- issue MMAs ----
        if (wid == 0 && elect_one()) {
            const uint64_t so = (uint64_t)b * (STAGE >> 4);
#pragma unroll
            for (int ks = 0; ks < 4; ++ks) {
                const uint64_t o = so + ks * 2;
                mma_bf16_ss(tmem, dAh0 + o, dBh0 + o, IDESC, !(t == 0 && ks == 0));
                mma_bf16_ss(tmem, dAh0 + o, dBl0 + o, IDESC, 1u);
                mma_bf16_ss(tmem, dAl0 + o, dBh0 + o, IDESC, 1u);
            }
            TC_COMMIT(mb);
        }
        if (b) use1++; else use0++;
    }
    if (use0 > 0) MBAR_WAIT(mb0, (use0 - 1) & 1);
    if (use1 > 0) MBAR_WAIT(mb1, (use1 - 1) & 1);
    TC_FENCE_AFTER();

    // ---- epilogue: both warpgroups read TMEM (subpartition = wid&3) ----
    const int sub = wid & 3;
    const int half = wid >> 2;
    const int mr = m0 + sub * 32 + lid;
    constexpr int CH = NT / 32;
    for (int c = half; c < CH; c += 2) {
        uint32_t r[32];
        TC_LD_X32(r, tmem + c * 32 + ((uint32_t)sub << 21));
        TC_WAIT_LD();
        const int nb = c * 32;
        if (mr < M && nb < Cout) {
#pragma unroll
            for (int j = 0; j < 32; j += 4) {
                float4 v;
                v.x = fmaxf(__uint_as_float(r[j + 0]), 0.f);
                v.y = fmaxf(__uint_as_float(r[j + 1]), 0.f);
                v.z = fmaxf(__uint_as_float(r[j + 2]), 0.f);
                v.w = fmaxf(__uint_as_float(r[j + 3]), 0.f);
                if (EPI == E_RES_RELU) {
                    const float4 rv = *reinterpret_cast<const float4*>(
                        res + (size_t)mr * Cout + nb + j);
                    v.x += rv.x; v.y += rv.y; v.z += rv.z; v.w += rv.w;
                }
                *reinterpret_cast<float4*>(out + (size_t)mr * Cout + nb + j) = v;
            }
        }
    }
    TC_FENCE_BEFORE();
    __syncthreads();
    if (tid == 0) { MBAR_INVAL(mb0); MBAR_INVAL(mb1); }
    __syncthreads();
    if (wid == 0) { TC_RELINQ(); TC_DEALLOC(tmem, 256); }
}

// ---------------- weight conversion: W[K][Cout] fp32 -> [Npad][Kpad] bf16 hi/lo
__global__ void conv_w(const float* __restrict__ W, uint4* __restrict__ Wh,
                       uint4* __restrict__ Wl, int Kdim, int Cout, int Kpad, int Npad)
{
    const int i = blockIdx.x * 256 + threadIdx.x;
    const int total = Npad * Kpad;
    if (i >= total) return;
    const int n = i / Kpad, k = i - n * Kpad;
    float x = 0.f;
    if (n < Cout && k < Kdim) x = W[(size_t)k * Cout + n];
    const __nv_bfloat16 h = __float2bfloat16_rn(x);
    const float hf = __bfloat162float(h);
    const __nv_bfloat16 l = __float2bfloat16_rn(x - hf);
    reinterpret_cast<__nv_bfloat16*>(Wh)[i] = h;
    reinterpret_cast<__nv_bfloat16*>(Wl)[i] = l;
}

// ---------------- SIMT GEMM for the final seed projection ----------------
template <int BM, int BN, int BK, int TM, int TN>
__global__ __launch_bounds__((BM / TM) * (BN / TN), 2) void gemm_final(
    const float* __restrict__ fA, const int* __restrict__ idx,
    const float* __restrict__ W, float* __restrict__ out,
    int M, int Cout, int Kdim)
{
    constexpr int THREADS = (BM / TM) * (BN / TN);
    constexpr int BMP = BM + 4;
    constexpr int A4 = BM * BK / 4;
    constexpr int B4 = BK * BN / 4;
    constexpr int NA = (A4 + THREADS - 1) / THREADS;
    constexpr int NB = (B4 + THREADS - 1) / THREADS;
    constexpr int BK4 = BK / 4;
    constexpr int BN4 = BN / 4;

    __shared__ __align__(16) float As[2][BK][BMP];
    __shared__ __align__(16) float Bs[2][BK][BN];

    const int tid = threadIdx.x;
    const int m0 = blockIdx.x * BM;
    const int n0 = blockIdx.y * BN;
    const int tx = tid % (BN / TN);
    const int ty = tid / (BN / TN);

    float4 ra[NA], rb[NB];
    float acc[TM][TN] = {};
    const int ntile = Kdim / BK;

    auto load_tile = [&](int it) {
        const int kt = it * BK;
#pragma unroll
        for (int t = 0; t < NA; ++t) {
            const int i4 = tid + t * THREADS;
            if (i4 < A4) {
                const int row = i4 / BK4;
                const int c4 = (i4 - row * BK4) * 4;
                const int m = m0 + row;
                float4 v = make_float4(0.f, 0.f, 0.f, 0.f);
                if (m < M) {
                    const int g = idx[m];
                    v = *reinterpret_cast<const float4*>(fA + (size_t)g * Kdim + kt + c4);
                }
                ra[t] = v;
            }
        }
#pragma unroll
        for (int t = 0; t < NB; ++t) {
            const int i4 = tid + t * THREADS;
            if (i4 < B4) {
                const int row = i4 / BN4;
                const int c = (i4 - row * BN4) * 4;
                rb[t] = *reinterpret_cast<const float4*>(W + (size_t)(kt + row) * Cout + n0 + c);
            }
        }
    };
    auto store_tile = [&](int buf) {
#pragma unroll
        for (int t = 0; t < NA; ++t) {
            const int i4 = tid + t * THREADS;
            if (i4 < A4) {
                const int row = i4 / BK4;
                const int c4 = (i4 - row * BK4) * 4;
                As[buf][c4 + 0][row] = ra[t].x;
                As[buf][c4 + 1][row] = ra[t].y;
                As[buf][c4 + 2][row] = ra[t].z;
                As[buf][c4 + 3][row] = ra[t].w;
            }
        }
#pragma unroll
        for (int t = 0; t < NB; ++t) {
            const int i4 = tid + t * THREADS;
            if (i4 < B4) {
                const int row = i4 / BN4;
                const int c = (i4 - row * BN4) * 4;
                *reinterpret_cast<float4*>(&Bs[buf][row][c]) = rb[t];
            }
        }
    };

    load_tile(0); store_tile(0); __syncthreads();
    int buf = 0;
    for (int it = 0; it < ntile; ++it) {
        if (it + 1 < ntile) load_tile(it + 1);
#pragma unroll
        for (int kk = 0; kk < BK; ++kk) {
            float a[TM], b[TN];
#pragma unroll
            for (int i = 0; i < TM; i += 4) {
                const float4 v = *reinterpret_cast<const float4*>(&As[buf][kk][ty * TM + i]);
                a[i] = v.x; a[i + 1] = v.y; a[i + 2] = v.z; a[i + 3] = v.w;
            }
#pragma unroll
            for (int j = 0; j < TN; j += 4) {
                const float4 v = *reinterpret_cast<const float4*>(&Bs[buf][kk][tx * TN + j]);
                b[j] = v.x; b[j + 1] = v.y; b[j + 2] = v.z; b[j + 3] = v.w;
            }
#pragma unroll
            for (int i = 0; i < TM; ++i)
#pragma unroll
                for (int j = 0; j < TN; ++j)
                    acc[i][j] = fmaf(a[i], b[j], acc[i][j]);
        }
        if (it + 1 < ntile) store_tile(buf ^ 1);
        __syncthreads();
        buf ^= 1;
    }
#pragma unroll
    for (int i = 0; i < TM; ++i) {
        const int mm = m0 + ty * TM + i;
        if (mm >= M) continue;
        const int bb = mm >> 10, ss = mm & 1023;
#pragma unroll
        for (int j = 0; j < TN; ++j) {
            const int n = n0 + tx * TN + j;
            out[((size_t)bb * Cout + n) * 1024 + ss] = acc[i][j];
        }
    }
}

// Stem: Cin=3 -> dedicated SIMT kernel.
__global__ __launch_bounds__(256) void stem_k(
    const float* __restrict__ feats, const int* __restrict__ nbr,
    const float* __restrict__ W, float* __restrict__ out, int M)
{
    __shared__ float sW[27 * 3 * 32];
    __shared__ float sg[8][81];
    __shared__ int   sidx[8][27];
    const int tid = threadIdx.x;
    const int m0 = blockIdx.x * 8;

    for (int i = tid; i < 27 * 96; i += 256) sW[i] = W[i];
    for (int i = tid; i < 8 * 27; i += 256) {
        const int r = i / 27, k = i % 27;
        const int m = m0 + r;
        sidx[r][k] = (m < M) ? nbr[(size_t)m * 27 + k] : 0;
    }
    __syncthreads();
    for (int i = tid; i < 8 * 81; i += 256) {
        const int r = i / 81, j = i % 81;
        sg[r][j] = feats[(size_t)sidx[r][j / 3] * 3 + (j % 3)];
    }
    __syncthreads();
    const int r = tid >> 5, co = tid & 31;
    const int m = m0 + r;
    float acc = 0.f;
#pragma unroll
    for (int j = 0; j < 81; ++j)
        acc = fmaf(sg[r][j], sW[j * 32 + co], acc);
    if (m < M) out[(size_t)m * 32 + co] = fmaxf(acc, 0.f);
}

static float* symf(const void* s) { void* p = nullptr; cudaGetSymbolAddress(&p, s); return (float*)p; }
static uint4* sym4(const void* s) { void* p = nullptr; cudaGetSymbolAddress(&p, s); return (uint4*)p; }

extern "C" void kernel_launch(void* const* d_in, const int* in_sizes, int n_in,
                              void* d_out, int out_size)
{
    const float* feats  = (const float*)d_in[0];
    const int* nbr0     = (const int*)d_in[1];
    const int* nbr1     = (const int*)d_in[2];
    const int* nbr2     = (const int*)d_in[3];
    const int* nbr3     = (const int*)d_in[4];
    const int* down1    = (const int*)d_in[5];
    const int* down2    = (const int*)d_in[6];
    const int* down3    = (const int*)d_in[7];
    const int* up2      = (const int*)d_in[8];
    const int* up1      = (const int*)d_in[9];
    const int* up0      = (const int*)d_in[10];
    const int* seed_idx = (const int*)d_in[11];
    const float* W_stem = (const float*)d_in[12];
    const float* W_b0   = (const float*)d_in[13];
    const float* W_d1   = (const float*)d_in[14];
    const float* W_b1   = (const float*)d_in[15];
    const float* W_d2   = (const float*)d_in[16];
    const float* W_b2   = (const float*)d_in[17];
    const float* W_d3   = (const float*)d_in[18];
    const float* W_b3   = (const float*)d_in[19];
    const float* W_u2   = (const float*)d_in[20];
    const float* W_u1   = (const float*)d_in[21];
    const float* W_u0   = (const float*)d_in[22];
    const float* W_out  = (const float*)d_in[23];
    float* out = (float*)d_out;

    float* x0a = symf(g_x0a); float* x0b = symf(g_x0b);
    float* x1a = symf(g_x1a); float* x1b = symf(g_x1b);
    float* x2a = symf(g_x2a); float* x2b = symf(g_x2b);
    float* x3a = symf(g_x3a); float* x3b = symf(g_x3b);
    float* u2  = symf(g_u2);  float* u1  = symf(g_u1);  float* u0 = symf(g_u0);

    const int SM32  = (2 * 128 * 128 + 2 * 32 * 128) * 2 + 1024;
    const int SM64  = (2 * 128 * 128 + 2 * 64 * 128) * 2 + 1024;
    const int SM128 = (2 * 128 * 128 + 2 * 128 * 128) * 2 + 1024;
    const int SM256 = (2 * 128 * 128 + 2 * 256 * 128) * 2 + 1024;
    cudaFuncSetAttribute(tc_gemm<32,  A_CONV,   E_RES_RELU>, cudaFuncAttributeMaxDynamicSharedMemorySize, SM32);
    cudaFuncSetAttribute(tc_gemm<64,  A_CONV,   E_RELU>,     cudaFuncAttributeMaxDynamicSharedMemorySize, SM64);
    cudaFuncSetAttribute(tc_gemm<64,  A_CONV,   E_RES_RELU>, cudaFuncAttributeMaxDynamicSharedMemorySize, SM64);
    cudaFuncSetAttribute(tc_gemm<128, A_CONV,   E_RELU>,     cudaFuncAttributeMaxDynamicSharedMemorySize, SM128);
    cudaFuncSetAttribute(tc_gemm<128, A_CONV,   E_RES_RELU>, cudaFuncAttributeMaxDynamicSharedMemorySize, SM128);
    cudaFuncSetAttribute(tc_gemm<128, A_CONCAT, E_RELU>,     cudaFuncAttributeMaxDynamicSharedMemorySize, SM128);
    cudaFuncSetAttribute(tc_gemm<256, A_CONV,   E_RELU>,     cudaFuncAttributeMaxDynamicSharedMemorySize, SM256);
    cudaFuncSetAttribute(tc_gemm<256, A_CONV,   E_RES_RELU>, cudaFuncAttributeMaxDynamicSharedMemorySize, SM256);
    cudaFuncSetAttribute(tc_gemm<256, A_CONCAT, E_RELU>,     cudaFuncAttributeMaxDynamicSharedMemorySize, SM256);

    auto cw = [&](const float* W, uint4* Wh, uint4* Wl, int Kd, int Co, int Kp, int Np) {
        const int total = Np * Kp;
        conv_w<<<(total + 255) / 256, 256>>>(W, Wh, Wl, Kd, Co, Kp, Np);
    };
    cw(W_b0, sym4(w_b0h), sym4(w_b0l),  864,  32,  896,  32);
    cw(W_d1, sym4(w_d1h), sym4(w_d1l),  256,  64,  256,  64);
    cw(W_b1, sym4(w_b1h), sym4(w_b1l), 1728,  64, 1728,  64);
    cw(W_d2, sym4(w_d2h), sym4(w_d2l),  512, 128,  512, 128);
    cw(W_b2, sym4(w_b2h), sym4(w_b2l), 3456, 128, 3456, 128);
    cw(W_d3, sym4(w_d3h), sym4(w_d3l), 1024, 256, 1024, 256);
    cw(W_b3, sym4(w_b3h), sym4(w_b3l), 6912, 256, 6912, 256);
    cw(W_u2, sym4(w_u2h), sym4(w_u2l),  384, 256,  384, 256);
    cw(W_u1, sym4(w_u1h), sym4(w_u1l),  320, 128,  320, 128);
    cw(W_u0, sym4(w_u0h), sym4(w_u0l),  160,  96,  192, 128);

    const int M0 = KN0, M1 = KN1, M2 = KN2, M3 = KN3;
    auto g = [](int M) { return (unsigned)((M + 127) / 128); };

    // ---- encoder ----
    stem_k<<<(M0 + 7) / 8, 256>>>(feats, nbr0, W_stem, x0a, M0);

    tc_gemm<32, A_CONV, E_RES_RELU><<<g(M0), 256, SM32>>>(
        x0a, nullptr, nbr0, sym4(w_b0h), sym4(w_b0l), x0a, x0b,
        M0, 32, 864, 896, 32, 27, 0);

    tc_gemm<64, A_CONV, E_RELU><<<g(M1), 256, SM64>>>(
        x0b, nullptr, down1, sym4(w_d1h), sym4(w_d1l), nullptr, x1a,
        M1, 64, 256, 256, 32, 8, 0);
    tc_gemm<64, A_CONV, E_RES_RELU><<<g(M1), 256, SM64>>>(
        x1a, nullptr, nbr1, sym4(w_b1h), sym4(w_b1l), x1a, x1b,
        M1, 64, 1728, 1728, 64, 27, 0);

    tc_gemm<128, A_CONV, E_RELU><<<g(M2), 256, SM128>>>(
        x1b, nullptr, down2, sym4(w_d2h), sym4(w_d2l), nullptr, x2a,
        M2, 128, 512, 512, 64, 8, 0);
    tc_gemm<128, A_CONV, E_RES_RELU><<<g(M2), 256, SM128>>>(
        x2a, nullptr, nbr2, sym4(w_b2h), sym4(w_b2l), x2a, x2b,
        M2, 128, 3456, 3456, 128, 27, 0);

    tc_gemm<256, A_CONV, E_RELU><<<g(M3), 256, SM256>>>(
        x2b, nullptr, down3, sym4(w_d3h), sym4(w_d3l), nullptr, x3a,
        M3, 256, 1024, 1024, 128, 8, 0);
    tc_gemm<256, A_CONV, E_RES_RELU><<<g(M3), 256, SM256>>>(
        x3a, nullptr, nbr3, sym4(w_b3h), sym4(w_b3l), x3a, x3b,
        M3, 256, 6912, 6912, 256, 27, 0);

    // ---- decoder ----
    tc_gemm<256, A_CONCAT, E_RELU><<<g(M2), 256, SM256>>>(
        x3b, x2b, up2, sym4(w_u2h), sym4(w_u2l), nullptr, u2,
        M2, 256, 384, 384, 0, 0, 256);
    tc_gemm<128, A_CONCAT, E_RELU><<<g(M1), 256, SM128>>>(
        u2, x1b, up1, sym4(w_u1h), sym4(w_u1l), nullptr, u1,
        M1, 128, 320, 320, 0, 0, 256);
    tc_gemm<128, A_CONCAT, E_RELU><<<g(M0), 256, SM128>>>(
        u1, x0b, up0, sym4(w_u0h), sym4(w_u0l), nullptr, u0,
        M0, 96, 160, 192, 0, 0, 128);

    // ---- final: gather 8192 seed rows, project to 512, transpose-store ----
    gemm_final<128, 128, 16, 8, 8><<<dim3(64, 4), 256>>>(
        u0, seed_idx, W_out, out, 8 * 1024, 512, 96);
}